// round 1
// baseline (speedup 1.0000x reference)
#include <cuda_runtime.h>

// Locally-connected 2D: out[oy,ox] = sum_{ky,kx} x[oy+ky, ox+kx] * W[oy,ox,ky,kx]
// x: [450,450] f32, W: [436,436,15,15] f32, out: [436,436] f32.
// HBM-bound on streaming W (171 MB, zero reuse). One warp per output pixel:
// W reads fully coalesced, x reads hit L1/L2 (massive overlap between
// neighboring pixels' patches).

#define IN_H 450
#define IN_W 450
#define KH 15
#define KW 15
#define OH 436
#define OW 436
#define KSIZE (KH * KW)   // 225
#define NPIX (OH * OW)    // 190096

__global__ __launch_bounds__(256, 8)
void lc2d_kernel(const float* __restrict__ x,
                 const float* __restrict__ W,
                 float* __restrict__ out)
{
    const int warp_global = (blockIdx.x * blockDim.x + threadIdx.x) >> 5;
    const int lane = threadIdx.x & 31;
    if (warp_global >= NPIX) return;

    const int oy = warp_global / OW;
    const int ox = warp_global - oy * OW;

    const float* wp = W + (size_t)warp_global * KSIZE;
    const float* xp = x + oy * IN_W + ox;

    float sum = 0.0f;

    // 225 = 7*32 + 1. Lanes read lane + 32*i -> coalesced 128B per step.
#pragma unroll
    for (int i = 0; i < 8; i++) {
        const int k = lane + (i << 5);
        if (k < KSIZE) {
            const float wv = __ldcs(wp + k);          // stream W, don't pollute L2
            const int ky = k / KW;
            const int kx = k - ky * KW;
            const float xv = __ldg(xp + ky * IN_W + kx); // x: cached, huge reuse
            sum = fmaf(wv, xv, sum);
        }
    }

    // Warp reduction
#pragma unroll
    for (int off = 16; off > 0; off >>= 1)
        sum += __shfl_down_sync(0xffffffffu, sum, off);

    if (lane == 0)
        out[warp_global] = sum;
}

extern "C" void kernel_launch(void* const* d_in, const int* in_sizes, int n_in,
                              void* d_out, int out_size)
{
    const float* x = (const float*)d_in[0];
    const float* W = (const float*)d_in[1];
    float* out = (float*)d_out;

    const int threads = 256;               // 8 warps/block -> 8 pixels/block
    const int warps_per_block = threads / 32;
    const int blocks = (NPIX + warps_per_block - 1) / warps_per_block;

    lc2d_kernel<<<blocks, threads>>>(x, W, out);
}